// round 14
// baseline (speedup 1.0000x reference)
#include <cuda_runtime.h>
#include <math.h>

#define NT 256   // ntheta
#define NP 512   // nphi
#define NC 32    // channels
#define NL 128   // L

typedef unsigned long long u64;

// ---------- packed f32x2 helpers (sm_103a FFMA2) ----------
__device__ __forceinline__ u64 pk2(float a, float b) {
    u64 r; asm("mov.b64 %0,{%1,%2};" : "=l"(r) : "f"(a), "f"(b)); return r;
}
__device__ __forceinline__ float2 upk(u64 v) {
    float2 f; asm("mov.b64 {%0,%1},%2;" : "=f"(f.x), "=f"(f.y) : "l"(v)); return f;
}
__device__ __forceinline__ u64 fma2(u64 a, u64 b, u64 c) {
    u64 d; asm("fma.rn.f32x2 %0,%1,%2,%3;" : "=l"(d) : "l"(a), "l"(b), "l"(c)); return d;
}
__device__ __forceinline__ u64 mul2(u64 a, u64 b) {
    u64 d; asm("mul.rn.f32x2 %0,%1,%2;" : "=l"(d) : "l"(a), "l"(b)); return d;
}
// ---------- PDL ----------
__device__ __forceinline__ void gdc_launch() {
    asm volatile("griddepcontrol.launch_dependents;" ::: "memory");
}
__device__ __forceinline__ void gdc_wait() {
    asm volatile("griddepcontrol.wait;" ::: "memory");
}

// ---------- static device scratch ----------
__device__ u64 g_F  [NT][NL][NC];
__device__ u64 g_flm[NL][NL][NC];
__device__ u64 g_uv [NL][NL][NC];
__device__ u64 g_AB [NT][NL][NC];

// ============================================================
// K1: forward DFT over phi, radix-2 + q-reflection folded.
// grid (256 t, 2 cg), block 128 (m-slots), smem 32KB (own 16 channels).
// ============================================================
__global__ __launch_bounds__(128) void k1_dft(const float* __restrict__ x,
                                              const float* __restrict__ wq) {
    gdc_launch();
    extern __shared__ u64 sm1[];
    u64* ype = sm1;              // [256][8]
    u64* ymo = sm1 + 2048;       // [256][8]

    const int t    = blockIdx.x;
    const int cg   = blockIdx.y;            // channel group 0/1
    const int tid  = threadIdx.x;
    const int lane = tid & 31;
    const int wm   = tid >> 5;              // 0..3
    const int par  = wm >> 1;               // 0: even m, 1: odd m
    const int m    = 2 * (((wm & 1) << 5) + lane) + par;

    // ---- stage parity-combined, scale-folded rows (16 channels) ----
    {
        const float s = wq[t] * (2.0f * (float)M_PI / 512.0f);
        const float4* x4 = (const float4*)(x + (size_t)t * NP * NC);
        for (int i = tid; i < 1024; i += 128) {
            const int p = i >> 2, j = i & 3;
            float4 a = x4[p * 8 + cg * 4 + j];
            float4 b = x4[(p + 256) * 8 + cg * 4 + j];
            ype[p * 8 + j * 2]     = pk2((a.x + b.x) * s, (a.y + b.y) * s);
            ype[p * 8 + j * 2 + 1] = pk2((a.z + b.z) * s, (a.w + b.w) * s);
            ymo[p * 8 + j * 2]     = pk2((a.x - b.x) * s, (a.y - b.y) * s);
            ymo[p * 8 + j * 2 + 1] = pk2((a.z - b.z) * s, (a.w - b.w) * s);
        }
    }
    __syncthreads();

    // ---- in-place reflection fold over rows q=1..127 ----
    {
        const u64 ONE2 = pk2(1.0f, 1.0f), NEG2 = pk2(-1.0f, -1.0f);
        for (int i = tid; i < 2048; i += 128) {
            const int q = (i >> 3) & 127;
            if (q == 0) continue;
            u64* base = sm1 + ((i >> 10) << 11);   // ype or ymo
            const int j  = i & 7;
            const int ia = q * 8 + j, ib = (256 - q) * 8 + j;
            u64 a = base[ia], b = base[ib];
            base[ia] = fma2(b, ONE2, a);
            base[ib] = fma2(b, NEG2, a);
        }
    }
    __syncthreads();

    const u64* yrow = par ? ymo : ype;

    float sd, cd;
    sincosf(-(float)M_PI / 256.0f * (float)m, &sd, &cd);
    u64 CDD = pk2(cd, cd), SDD = pk2(sd, sd), NSD = pk2(-sd, -sd);
    u64 CC = pk2(cd, cd), SS = pk2(sd, sd);   // state at q=1

    u64 aR[8], aI[8];
#pragma unroll
    for (int k = 0; k < 8; k++) { aR[k] = 0ull; aI[k] = 0ull; }

    const u64* pR = yrow + (par ? 255 * 8 : 8);
    const u64* pI = yrow + (par ? 8 : 255 * 8);
    const int  sR = par ? -8 : 8;

#pragma unroll 2
    for (int q = 1; q < 128; q++) {
        const ulonglong2* rR = (const ulonglong2*)pR;
        const ulonglong2* rI = (const ulonglong2*)pI;
#pragma unroll
        for (int k = 0; k < 4; k++) {
            ulonglong2 vR = rR[k];
            ulonglong2 vI = rI[k];
            aR[2 * k]     = fma2(vR.x, CC, aR[2 * k]);
            aR[2 * k + 1] = fma2(vR.y, CC, aR[2 * k + 1]);
            aI[2 * k]     = fma2(vI.x, SS, aI[2 * k]);
            aI[2 * k + 1] = fma2(vI.y, SS, aI[2 * k + 1]);
        }
        u64 t1 = mul2(SS, NSD);
        u64 nC = fma2(CC, CDD, t1);
        u64 t2 = mul2(CC, SDD);
        SS = fma2(SS, CDD, t2);
        CC = nC;
        pR += sR; pI -= sR;
    }

    // ---- edge terms q=0 and q=128 ----
    {
        const ulonglong2* r0 = (const ulonglong2*)yrow;
        const ulonglong2* rh = (const ulonglong2*)(yrow + 128 * 8);
        const float sg = ((m >> 1) & 1) ? -1.0f : 1.0f;
        const u64 ONE2 = pk2(1.0f, 1.0f);
        if (!par) {
            const u64 SG = pk2(sg, sg);
#pragma unroll
            for (int k = 0; k < 4; k++) {
                ulonglong2 v0 = r0[k], vh = rh[k];
                aR[2 * k]     = fma2(v0.x, ONE2, aR[2 * k]);
                aR[2 * k + 1] = fma2(v0.y, ONE2, aR[2 * k + 1]);
                aR[2 * k]     = fma2(vh.x, SG, aR[2 * k]);
                aR[2 * k + 1] = fma2(vh.y, SG, aR[2 * k + 1]);
            }
        } else {
            const u64 SG = pk2(-sg, -sg);
#pragma unroll
            for (int k = 0; k < 4; k++) {
                ulonglong2 v0 = r0[k], vh = rh[k];
                aR[2 * k]     = fma2(v0.x, ONE2, aR[2 * k]);
                aR[2 * k + 1] = fma2(v0.y, ONE2, aR[2 * k + 1]);
                aI[2 * k]     = fma2(vh.x, SG, aI[2 * k]);
                aI[2 * k + 1] = fma2(vh.y, SG, aI[2 * k + 1]);
            }
        }
    }

    ulonglong2* fout = (ulonglong2*)&g_F[t][m][cg * 16];
#pragma unroll
    for (int k = 0; k < 8; k++) {
        float2 r = upk(aR[k]), i2 = upk(aI[k]);
        fout[k] = make_ulonglong2(pk2(r.x, i2.x), pk2(r.y, i2.y));
    }
}

// ============================================================
// K2: Legendre analysis, NO smem: Fp/Fm computed in-loop from
// coalesced g_F loads (L1 broadcast-hot across the 8 warps).
// grid (64 mp, 4 lh), block 256. Zero barriers.
// ============================================================
__global__ __launch_bounds__(256) void k2_analysis(const float* __restrict__ leg) {
    gdc_launch();
    const int mp   = blockIdx.x;
    const int lh   = blockIdx.y;
    const int tid  = threadIdx.x;
    const int w    = tid >> 5;
    const int lane = tid & 31;

    gdc_wait();

    const u64 ONE2 = pk2(1.0f, 1.0f), NEG2 = pk2(-1.0f, -1.0f);

    for (int half = 0; half < 2; half++) {
        const int m  = half ? (127 - mp) : mp;
        const int nl = NL - m;

        const int li = (lh * 8 + w) * 4;
        if (li >= nl) continue;

        u64 acc[4] = {0ull, 0ull, 0ull, 0ull};
        const int lmax = min(4, nl - li);
        const float* bp[4];
#pragma unroll
        for (int k = 0; k < 4; k++) {
            int l = m + li + k; if (l > 127) l = 127;
            bp[k] = leg + ((size_t)l * 255 + (127 + m)) * NT;
        }
#pragma unroll 4
        for (int t = 0; t < 128; t++) {
            u64 a = __ldg(&g_F[t][m][lane]);
            u64 b = __ldg(&g_F[255 - t][m][lane]);
            u64 fp = fma2(b, ONE2, a);
            u64 fm = fma2(b, NEG2, a);
#pragma unroll
            for (int k = 0; k < 4; k++) {
                float bb = __ldg(bp[k] + t);
                acc[k] = fma2(pk2(bb, bb), (k & 1) ? fm : fp, acc[k]);
            }
        }
        for (int k = 0; k < lmax; k++)
            g_flm[m][m + li + k][lane] = acc[k];
    }
}

// ============================================================
// K3: channel mix; 1D grid over the 8256 valid (l,m) pairs only.
// Weight prefetch before gdc_wait overlaps K2.
// ============================================================
__global__ __launch_bounds__(256) void k3_mix(const float* __restrict__ Wr,
                                              const float* __restrict__ Wi) {
    gdc_launch();
    const int i = blockIdx.x;
    int l = (int)((sqrtf(8.0f * (float)i + 1.0f) - 1.0f) * 0.5f);
    while ((l + 1) * (l + 2) / 2 <= i) ++l;
    while (l * (l + 1) / 2 > i) --l;
    const int m = i - l * (l + 1) / 2;

    __shared__ float2 sf[32];
    __shared__ float2 red[8][32];
    const int tid = threadIdx.x, w = tid >> 5, lane = tid & 31;

    const size_t bp = ((size_t)l * 255 + (127 + m)) * 1024;
    const size_t bn = ((size_t)l * 255 + (127 - m)) * 1024;

    float S[4], D[4];
#pragma unroll
    for (int k = 0; k < 4; k++) {
        const int c = w * 4 + k;
        const size_t op = bp + (size_t)c * 32 + lane;
        float wr = __ldcs(Wr + op);
        float wi = __ldcs(Wi + op);
        if (m) {
            const size_t on = bn + (size_t)c * 32 + lane;
            S[k] = wr + __ldcs(Wr + on);
            D[k] = __ldcs(Wi + on) - wi;
        } else {
            S[k] = wr; D[k] = -wi;
        }
    }

    gdc_wait();

    if (tid < 32) sf[tid] = ((const float2*)&g_flm[m][l][0])[tid];
    __syncthreads();

    float U = 0.0f, V = 0.0f;
#pragma unroll
    for (int k = 0; k < 4; k++) {
        const int c = w * 4 + k;
        const float fr = sf[c].x, fi = sf[c].y;
        U += fr * S[k]; U += fi * D[k];
        V += fr * D[k]; V -= fi * S[k];
    }
    red[w][lane] = make_float2(U, V);
    __syncthreads();
    if (w == 0) {
        float2 a = red[0][lane];
#pragma unroll
        for (int k = 1; k < 8; k++) { a.x += red[k][lane].x; a.y += red[k][lane].y; }
        g_uv[m][l][lane] = pk2(a.x, a.y);
    }
}

// ============================================================
// K4: Legendre synthesis. P in static smem (16KB); uv read in-loop
// via coalesced __ldg (L2/L1-hot, shared across tg blocks).
// 16KB smem -> up to 8 blocks/SM (64 warps).
// grid (128 m, 4 tg), block 256 = 8 warps x 4 t, lane = o.
// ============================================================
__global__ __launch_bounds__(256) void k4_synth(const float* __restrict__ leg) {
    gdc_launch();
    __shared__ float sP[128 * 32];   // 16 KB

    const int m   = blockIdx.x;
    const int tg  = blockIdx.y;
    const int nl  = NL - m;
    const int nlp = (nl + 3) & ~3;
    const int tid = threadIdx.x, w = tid >> 5, lane = tid & 31;
    const int tb  = w * 4;

    // ---- stage P (independent of K3; overlaps it) ----
    const float* Pp = leg + ((size_t)m * 255 + (127 + m)) * NT + tg * 32;
    for (int i = tid; i < nlp * 32; i += 256) {
        const int il = i >> 5, tt = i & 31;
        sP[i] = (il < nl) ? __ldg(Pp + (size_t)il * (255 * NT) + tt) : 0.0f;
    }

    gdc_wait();   // g_uv ready
    __syncthreads();

    const u64* uvp = &g_uv[m][m][0];

    u64 E[4] = {0ull, 0ull, 0ull, 0ull};
    u64 O[4] = {0ull, 0ull, 0ull, 0ull};

#pragma unroll 2
    for (int il = 0; il < nlp; il += 2) {
        const int i0 = min(il, nl - 1), i1 = min(il + 1, nl - 1);
        const u64 uv0 = __ldg(uvp + i0 * 32 + lane);
        const u64 uv1 = __ldg(uvp + i1 * 32 + lane);
        const float4 P0 = *(const float4*)(sP + il * 32 + tb);
        const float4 P1 = *(const float4*)(sP + (il + 1) * 32 + tb);
        E[0] = fma2(pk2(P0.x, P0.x), uv0, E[0]);
        E[1] = fma2(pk2(P0.y, P0.y), uv0, E[1]);
        E[2] = fma2(pk2(P0.z, P0.z), uv0, E[2]);
        E[3] = fma2(pk2(P0.w, P0.w), uv0, E[3]);
        O[0] = fma2(pk2(P1.x, P1.x), uv1, O[0]);
        O[1] = fma2(pk2(P1.y, P1.y), uv1, O[1]);
        O[2] = fma2(pk2(P1.z, P1.z), uv1, O[2]);
        O[3] = fma2(pk2(P1.w, P1.w), uv1, O[3]);
    }

#pragma unroll
    for (int j = 0; j < 4; j++) {
        const int t = tg * 32 + tb + j;
        float2 e = upk(E[j]), o2 = upk(O[j]);
        g_AB[t][m][lane]       = pk2(e.x + o2.x, e.y + o2.y);
        g_AB[255 - t][m][lane] = pk2(e.x - o2.x, e.y - o2.y);
    }
}

// ============================================================
// K5: inverse transform, m-parity + p-reflection folded, edge fused.
// grid (256 t, 2 og), block 128 (p).
// ============================================================
__global__ __launch_bounds__(128) void k5_idft(float* __restrict__ out) {
    __shared__ u64 sAB[128 * 16];    // 16 KB
    __shared__ float redu[8][16], redv[8][16];
    const int t  = blockIdx.x;
    const int ob = blockIdx.y * 16;
    const int p  = threadIdx.x;      // 0..127

    gdc_wait();

    for (int i = p; i < 128 * 16; i += 128) {
        const int m = i >> 4, o = i & 15;
        sAB[i] = g_AB[t][m][ob + o];
    }
    __syncthreads();

    u64 E[16], O[16];
#pragma unroll
    for (int k = 0; k < 16; k++) { E[k] = 0ull; O[k] = 0ull; }

    float sd, cd;
    sincosf(((float)M_PI / 256.0f) * (float)p, &sd, &cd);
    u64 CDD = pk2(cd, cd);
    u64 P1 = pk2(-sd, sd), P2 = pk2(sd, -sd);
    u64 cs = pk2(1.0f, 0.0f), sc = pk2(0.0f, 1.0f);

#pragma unroll 2
    for (int m = 0; m < 128; m += 2) {
        const ulonglong2* r0 = (const ulonglong2*)(sAB + m * 16);
#pragma unroll
        for (int k = 0; k < 8; k++) {
            ulonglong2 v = r0[k];
            E[2 * k]     = fma2(v.x, cs, E[2 * k]);
            E[2 * k + 1] = fma2(v.y, cs, E[2 * k + 1]);
        }
        { u64 t1 = mul2(sc, P1); u64 nc = fma2(cs, CDD, t1);
          u64 t2 = mul2(cs, P2); sc = fma2(sc, CDD, t2); cs = nc; }

        const ulonglong2* r1 = (const ulonglong2*)(sAB + (m + 1) * 16);
#pragma unroll
        for (int k = 0; k < 8; k++) {
            ulonglong2 v = r1[k];
            O[2 * k]     = fma2(v.x, cs, O[2 * k]);
            O[2 * k + 1] = fma2(v.y, cs, O[2 * k + 1]);
        }
        { u64 t1 = mul2(sc, P1); u64 nc = fma2(cs, CDD, t1);
          u64 t2 = mul2(cs, P2); sc = fma2(sc, CDD, t2); cs = nc; }
    }

#pragma unroll
    for (int k = 0; k < 16; k++) {
        float2 e = upk(E[k]), o2 = upk(O[k]);
        const float s1 = e.x + e.y, s2 = e.x - e.y;
        const float d1 = o2.x + o2.y, d2 = o2.x - o2.y;
        const size_t base = ((size_t)(ob + k) * NT + t) * NP;
        out[base + p]       = s1 + d1;
        out[base + 256 + p] = s1 - d1;
        out[base + 256 - p] = s2 - d2;
        if (p) out[base + 512 - p] = s2 + d2;
    }

    {
        const int seg = p >> 4, o = p & 15;
        float u = 0.0f, v = 0.0f;
#pragma unroll
        for (int k = 0; k < 16; k++) {
            const int m = seg * 16 + k;
            float2 val = upk(sAB[m * 16 + o]);
            if (m & 1) v += (m & 2) ? -val.y : val.y;
            else       u += (m & 2) ? -val.x : val.x;
        }
        redu[seg][o] = u; redv[seg][o] = v;
        __syncthreads();
        if (seg == 0) {
            float U = 0.0f, V = 0.0f;
#pragma unroll
            for (int s = 0; s < 8; s++) { U += redu[s][o]; V += redv[s][o]; }
            const size_t base = ((size_t)(ob + o) * NT + t) * NP;
            out[base + 128] = U + V;
            out[base + 384] = U - V;
        }
    }
}

// ============================================================
extern "C" void kernel_launch(void* const* d_in, const int* in_sizes, int n_in,
                              void* d_out, int out_size) {
    const float* x   = (const float*)d_in[0];
    const float* Wr  = (const float*)d_in[1];
    const float* Wi  = (const float*)d_in[2];
    const float* leg = (const float*)d_in[3];
    const float* wq  = (const float*)d_in[4];
    float* out = (float*)d_out;

    cudaLaunchAttribute pdl[1];
    pdl[0].id = cudaLaunchAttributeProgrammaticStreamSerialization;
    pdl[0].val.programmaticStreamSerializationAllowed = 1;

    k1_dft<<<dim3(256, 2), 128, 32768>>>(x, wq);

    {
        cudaLaunchConfig_t c{};
        c.gridDim = dim3(64, 4); c.blockDim = dim3(256);
        c.dynamicSmemBytes = 0; c.stream = 0;
        c.attrs = pdl; c.numAttrs = 1;
        cudaLaunchKernelEx(&c, k2_analysis, leg);
    }
    {
        cudaLaunchConfig_t c{};
        c.gridDim = dim3(8256); c.blockDim = dim3(256);
        c.dynamicSmemBytes = 0; c.stream = 0;
        c.attrs = pdl; c.numAttrs = 1;
        cudaLaunchKernelEx(&c, k3_mix, Wr, Wi);
    }
    {
        cudaLaunchConfig_t c{};
        c.gridDim = dim3(128, 4); c.blockDim = dim3(256);
        c.dynamicSmemBytes = 0; c.stream = 0;
        c.attrs = pdl; c.numAttrs = 1;
        cudaLaunchKernelEx(&c, k4_synth, leg);
    }
    {
        cudaLaunchConfig_t c{};
        c.gridDim = dim3(256, 2); c.blockDim = dim3(128);
        c.dynamicSmemBytes = 0; c.stream = 0;
        c.attrs = pdl; c.numAttrs = 1;
        cudaLaunchKernelEx(&c, k5_idft, out);
    }
}

// round 16
// speedup vs baseline: 1.6270x; 1.6270x over previous
#include <cuda_runtime.h>
#include <math.h>

#define NT 256   // ntheta
#define NP 512   // nphi
#define NC 32    // channels
#define NL 128   // L

typedef unsigned long long u64;

// ---------- packed f32x2 helpers (sm_103a FFMA2) ----------
__device__ __forceinline__ u64 pk2(float a, float b) {
    u64 r; asm("mov.b64 %0,{%1,%2};" : "=l"(r) : "f"(a), "f"(b)); return r;
}
__device__ __forceinline__ float2 upk(u64 v) {
    float2 f; asm("mov.b64 {%0,%1},%2;" : "=f"(f.x), "=f"(f.y) : "l"(v)); return f;
}
__device__ __forceinline__ u64 fma2(u64 a, u64 b, u64 c) {
    u64 d; asm("fma.rn.f32x2 %0,%1,%2,%3;" : "=l"(d) : "l"(a), "l"(b), "l"(c)); return d;
}
__device__ __forceinline__ u64 mul2(u64 a, u64 b) {
    u64 d; asm("mul.rn.f32x2 %0,%1,%2;" : "=l"(d) : "l"(a), "l"(b)); return d;
}
// ---------- PDL ----------
__device__ __forceinline__ void gdc_launch() {
    asm volatile("griddepcontrol.launch_dependents;" ::: "memory");
}
__device__ __forceinline__ void gdc_wait() {
    asm volatile("griddepcontrol.wait;" ::: "memory");
}

// ---------- static device scratch ----------
__device__ u64 g_F  [NT][NL][NC];
__device__ u64 g_flm[NL][NL][NC];
__device__ u64 g_uv [NL][NL][NC];
__device__ u64 g_AB [NT][NL][NC];

// ============================================================
// K1: forward DFT over phi, radix-2 + q-reflection folded.
// grid 256 (t), block 256 = 128 m-slots x 2 channel-groups (16 ch each).
// ============================================================
__global__ __launch_bounds__(256) void k1_dft(const float* __restrict__ x,
                                              const float* __restrict__ wq) {
    gdc_launch();
    extern __shared__ u64 sm1[];
    u64* ype = sm1;
    u64* ymo = sm1 + 4096;

    const int t    = blockIdx.x;
    const int tid  = threadIdx.x;
    const int lane = tid & 31;
    const int cg   = tid >> 7;              // channel group 0/1
    const int wm   = (tid & 127) >> 5;      // 0..3
    const int par  = wm >> 1;               // 0: even m, 1: odd m
    const int m    = 2 * (((wm & 1) << 5) + lane) + par;

    {
        const float s = wq[t] * (2.0f * (float)M_PI / 512.0f);
        const float4* x4 = (const float4*)(x + (size_t)t * NP * NC);
        for (int i = tid; i < 2048; i += 256) {
            float4 a = x4[i];
            float4 b = x4[i + 2048];
            const int p = i >> 3, j = i & 7;
            ype[p * 16 + j * 2]     = pk2((a.x + b.x) * s, (a.y + b.y) * s);
            ype[p * 16 + j * 2 + 1] = pk2((a.z + b.z) * s, (a.w + b.w) * s);
            ymo[p * 16 + j * 2]     = pk2((a.x - b.x) * s, (a.y - b.y) * s);
            ymo[p * 16 + j * 2 + 1] = pk2((a.z - b.z) * s, (a.w - b.w) * s);
        }
    }
    __syncthreads();

    {
        const u64 ONE2 = pk2(1.0f, 1.0f), NEG2 = pk2(-1.0f, -1.0f);
        for (int i = tid; i < 4096; i += 256) {
            const int q = (i >> 4) & 127;
            if (q == 0) continue;
            u64* base = sm1 + ((i >> 11) << 12);
            const int j  = i & 15;
            const int ia = q * 16 + j, ib = (256 - q) * 16 + j;
            u64 a = base[ia], b = base[ib];
            base[ia] = fma2(b, ONE2, a);
            base[ib] = fma2(b, NEG2, a);
        }
    }
    __syncthreads();

    const u64* yrow = (par ? ymo : ype) + cg * 8;

    float sd, cd;
    sincosf(-(float)M_PI / 256.0f * (float)m, &sd, &cd);
    u64 CDD = pk2(cd, cd), SDD = pk2(sd, sd), NSD = pk2(-sd, -sd);
    u64 CC = pk2(cd, cd), SS = pk2(sd, sd);   // state at q=1

    u64 aR[8], aI[8];
#pragma unroll
    for (int k = 0; k < 8; k++) { aR[k] = 0ull; aI[k] = 0ull; }

    const u64* pR = yrow + (par ? 255 * 16 : 16);
    const u64* pI = yrow + (par ? 16 : 255 * 16);
    const int  sR = par ? -16 : 16;

#pragma unroll 4
    for (int q = 1; q < 128; q++) {
        const ulonglong2* rR = (const ulonglong2*)pR;
        const ulonglong2* rI = (const ulonglong2*)pI;
#pragma unroll
        for (int k = 0; k < 4; k++) {
            ulonglong2 vR = rR[k];
            ulonglong2 vI = rI[k];
            aR[2 * k]     = fma2(vR.x, CC, aR[2 * k]);
            aR[2 * k + 1] = fma2(vR.y, CC, aR[2 * k + 1]);
            aI[2 * k]     = fma2(vI.x, SS, aI[2 * k]);
            aI[2 * k + 1] = fma2(vI.y, SS, aI[2 * k + 1]);
        }
        u64 t1 = mul2(SS, NSD);
        u64 nC = fma2(CC, CDD, t1);
        u64 t2 = mul2(CC, SDD);
        SS = fma2(SS, CDD, t2);
        CC = nC;
        pR += sR; pI -= sR;
    }

    {
        const ulonglong2* r0 = (const ulonglong2*)yrow;
        const ulonglong2* rh = (const ulonglong2*)(yrow + 128 * 16);
        const float sg = ((m >> 1) & 1) ? -1.0f : 1.0f;
        const u64 ONE2 = pk2(1.0f, 1.0f);
        if (!par) {
            const u64 SG = pk2(sg, sg);
#pragma unroll
            for (int k = 0; k < 4; k++) {
                ulonglong2 v0 = r0[k], vh = rh[k];
                aR[2 * k]     = fma2(v0.x, ONE2, aR[2 * k]);
                aR[2 * k + 1] = fma2(v0.y, ONE2, aR[2 * k + 1]);
                aR[2 * k]     = fma2(vh.x, SG, aR[2 * k]);
                aR[2 * k + 1] = fma2(vh.y, SG, aR[2 * k + 1]);
            }
        } else {
            const u64 SG = pk2(-sg, -sg);
#pragma unroll
            for (int k = 0; k < 4; k++) {
                ulonglong2 v0 = r0[k], vh = rh[k];
                aR[2 * k]     = fma2(v0.x, ONE2, aR[2 * k]);
                aR[2 * k + 1] = fma2(v0.y, ONE2, aR[2 * k + 1]);
                aI[2 * k]     = fma2(vh.x, SG, aI[2 * k]);
                aI[2 * k + 1] = fma2(vh.y, SG, aI[2 * k + 1]);
            }
        }
    }

    ulonglong2* fout = (ulonglong2*)&g_F[t][m][cg * 16];
#pragma unroll
    for (int k = 0; k < 8; k++) {
        float2 r = upk(aR[k]), i2 = upk(aI[k]);
        fout[k] = make_ulonglong2(pk2(r.x, i2.x), pk2(r.y, i2.y));
    }
}

// ============================================================
// K2: Legendre analysis, theta-parity folded, m-pair balanced,
// l-range split 4-way over blockIdx.y (256 blocks).
// ============================================================
__global__ __launch_bounds__(256) void k2_analysis(const float* __restrict__ leg) {
    gdc_launch();
    extern __shared__ u64 sm2[];
    u64* Fp = sm2;
    u64* Fm = sm2 + 128 * 32;

    const int mp   = blockIdx.x;
    const int lh   = blockIdx.y;
    const int tid  = threadIdx.x;
    const int w    = tid >> 5;
    const int lane = tid & 31;

    gdc_wait();

    for (int half = 0; half < 2; half++) {
        const int m  = half ? (127 - mp) : mp;
        const int nl = NL - m;

        __syncthreads();
        for (int i = tid; i < 128 * 32; i += 256) {
            const int t = i >> 5, c = i & 31;
            float2 a = upk(g_F[t][m][c]);
            float2 b = upk(g_F[255 - t][m][c]);
            Fp[i] = pk2(a.x + b.x, a.y + b.y);
            Fm[i] = pk2(a.x - b.x, a.y - b.y);
        }
        __syncthreads();

        for (int li = (lh * 8 + w) * 4; li < nl; li += 128) {
            u64 acc[4] = {0ull, 0ull, 0ull, 0ull};
            const int lmax = min(4, nl - li);
            const float* bp[4];
#pragma unroll
            for (int k = 0; k < 4; k++) {
                int l = m + li + k; if (l > 127) l = 127;
                bp[k] = leg + ((size_t)l * 255 + (127 + m)) * NT;
            }
#pragma unroll 4
            for (int t = 0; t < 128; t++) {
                u64 fp = Fp[t * 32 + lane];
                u64 fm = Fm[t * 32 + lane];
#pragma unroll
                for (int k = 0; k < 4; k++) {
                    float b = __ldg(bp[k] + t);
                    acc[k] = fma2(pk2(b, b), (k & 1) ? fm : fp, acc[k]);
                }
            }
            for (int k = 0; k < lmax; k++)
                g_flm[m][m + li + k][lane] = acc[k];
        }
    }
}

// ============================================================
// K3: channel mix; 1D grid over the 8256 valid (l,m) pairs only.
// Weight prefetch before gdc_wait overlaps K2.
// ============================================================
__global__ __launch_bounds__(256) void k3_mix(const float* __restrict__ Wr,
                                              const float* __restrict__ Wi) {
    gdc_launch();
    const int i = blockIdx.x;
    int l = (int)((sqrtf(8.0f * (float)i + 1.0f) - 1.0f) * 0.5f);
    while ((l + 1) * (l + 2) / 2 <= i) ++l;
    while (l * (l + 1) / 2 > i) --l;
    const int m = i - l * (l + 1) / 2;

    __shared__ float2 sf[32];
    __shared__ float2 red[8][32];
    const int tid = threadIdx.x, w = tid >> 5, lane = tid & 31;

    const size_t bp = ((size_t)l * 255 + (127 + m)) * 1024;
    const size_t bn = ((size_t)l * 255 + (127 - m)) * 1024;

    float S[4], D[4];
#pragma unroll
    for (int k = 0; k < 4; k++) {
        const int c = w * 4 + k;
        const size_t op = bp + (size_t)c * 32 + lane;
        float wr = __ldcs(Wr + op);
        float wi = __ldcs(Wi + op);
        if (m) {
            const size_t on = bn + (size_t)c * 32 + lane;
            S[k] = wr + __ldcs(Wr + on);
            D[k] = __ldcs(Wi + on) - wi;
        } else {
            S[k] = wr; D[k] = -wi;
        }
    }

    gdc_wait();

    if (tid < 32) sf[tid] = ((const float2*)&g_flm[m][l][0])[tid];
    __syncthreads();

    float U = 0.0f, V = 0.0f;
#pragma unroll
    for (int k = 0; k < 4; k++) {
        const int c = w * 4 + k;
        const float fr = sf[c].x, fi = sf[c].y;
        U += fr * S[k]; U += fi * D[k];
        V += fr * D[k]; V -= fi * S[k];
    }
    red[w][lane] = make_float2(U, V);
    __syncthreads();
    if (w == 0) {
        float2 a = red[0][lane];
#pragma unroll
        for (int k = 1; k < 8; k++) { a.x += red[k][lane].x; a.y += red[k][lane].y; }
        g_uv[m][l][lane] = pk2(a.x, a.y);
    }
}

// ============================================================
// K4: Legendre synthesis, all-smem inner loop, 48KB smem -> 4 blocks/SM,
// single wave at grid 512. P stored as plain float (packed in-loop).
// grid (128 m, 4 tg), block 256 = 8 warps x 4 t, lane = o.
// ============================================================
__global__ __launch_bounds__(256) void k4_synth(const float* __restrict__ leg) {
    gdc_launch();
    extern __shared__ u64 sm4[];
    u64*   suv = sm4;                       // [128][32] u64   (32KB)
    float* sP  = (float*)(sm4 + 128 * 32);  // [128][32] float (16KB)

    const int m   = blockIdx.x;
    const int tg  = blockIdx.y;
    const int nl  = NL - m;
    const int nlp = (nl + 3) & ~3;
    const int tid = threadIdx.x, w = tid >> 5, lane = tid & 31;
    const int tb  = w * 4;

    // ---- stage P (independent of K3; overlaps it) ----
    const float* Pp = leg + ((size_t)m * 255 + (127 + m)) * NT + tg * 32;
    for (int i = tid; i < nlp * 32; i += 256) {
        const int il = i >> 5, tt = i & 31;
        sP[i] = (il < nl) ? __ldg(Pp + (size_t)il * (255 * NT) + tt) : 0.0f;
    }

    gdc_wait();   // g_uv ready

    const u64* uvp = &g_uv[m][m][0];
    for (int i = tid; i < nlp * 32; i += 256)
        suv[i] = (i < nl * 32) ? uvp[i] : 0ull;
    __syncthreads();

    u64 E[4] = {0ull, 0ull, 0ull, 0ull};
    u64 O[4] = {0ull, 0ull, 0ull, 0ull};

#pragma unroll 4
    for (int il = 0; il < nlp; il += 2) {
        const u64 uv0 = suv[il * 32 + lane];
        const u64 uv1 = suv[(il + 1) * 32 + lane];
        const float4 P0 = *(const float4*)(sP + il * 32 + tb);
        const float4 P1 = *(const float4*)(sP + (il + 1) * 32 + tb);
        E[0] = fma2(pk2(P0.x, P0.x), uv0, E[0]);
        E[1] = fma2(pk2(P0.y, P0.y), uv0, E[1]);
        E[2] = fma2(pk2(P0.z, P0.z), uv0, E[2]);
        E[3] = fma2(pk2(P0.w, P0.w), uv0, E[3]);
        O[0] = fma2(pk2(P1.x, P1.x), uv1, O[0]);
        O[1] = fma2(pk2(P1.y, P1.y), uv1, O[1]);
        O[2] = fma2(pk2(P1.z, P1.z), uv1, O[2]);
        O[3] = fma2(pk2(P1.w, P1.w), uv1, O[3]);
    }

#pragma unroll
    for (int j = 0; j < 4; j++) {
        const int t = tg * 32 + tb + j;
        float2 e = upk(E[j]), o2 = upk(O[j]);
        g_AB[t][m][lane]       = pk2(e.x + o2.x, e.y + o2.y);
        g_AB[255 - t][m][lane] = pk2(e.x - o2.x, e.y - o2.y);
    }
}

// ============================================================
// K5: inverse transform, m-parity + p-reflection folded, edge fused.
// grid (256 t, 2 og), block 128 (p).
// ============================================================
__global__ __launch_bounds__(128) void k5_idft(float* __restrict__ out) {
    __shared__ u64 sAB[128 * 16];    // 16 KB
    __shared__ float redu[8][16], redv[8][16];
    const int t  = blockIdx.x;
    const int ob = blockIdx.y * 16;
    const int p  = threadIdx.x;      // 0..127

    gdc_wait();

    for (int i = p; i < 128 * 16; i += 128) {
        const int m = i >> 4, o = i & 15;
        sAB[i] = g_AB[t][m][ob + o];
    }
    __syncthreads();

    u64 E[16], O[16];
#pragma unroll
    for (int k = 0; k < 16; k++) { E[k] = 0ull; O[k] = 0ull; }

    float sd, cd;
    sincosf(((float)M_PI / 256.0f) * (float)p, &sd, &cd);
    u64 CDD = pk2(cd, cd);
    u64 P1 = pk2(-sd, sd), P2 = pk2(sd, -sd);
    u64 cs = pk2(1.0f, 0.0f), sc = pk2(0.0f, 1.0f);

#pragma unroll 2
    for (int m = 0; m < 128; m += 2) {
        const ulonglong2* r0 = (const ulonglong2*)(sAB + m * 16);
#pragma unroll
        for (int k = 0; k < 8; k++) {
            ulonglong2 v = r0[k];
            E[2 * k]     = fma2(v.x, cs, E[2 * k]);
            E[2 * k + 1] = fma2(v.y, cs, E[2 * k + 1]);
        }
        { u64 t1 = mul2(sc, P1); u64 nc = fma2(cs, CDD, t1);
          u64 t2 = mul2(cs, P2); sc = fma2(sc, CDD, t2); cs = nc; }

        const ulonglong2* r1 = (const ulonglong2*)(sAB + (m + 1) * 16);
#pragma unroll
        for (int k = 0; k < 8; k++) {
            ulonglong2 v = r1[k];
            O[2 * k]     = fma2(v.x, cs, O[2 * k]);
            O[2 * k + 1] = fma2(v.y, cs, O[2 * k + 1]);
        }
        { u64 t1 = mul2(sc, P1); u64 nc = fma2(cs, CDD, t1);
          u64 t2 = mul2(cs, P2); sc = fma2(sc, CDD, t2); cs = nc; }
    }

#pragma unroll
    for (int k = 0; k < 16; k++) {
        float2 e = upk(E[k]), o2 = upk(O[k]);
        const float s1 = e.x + e.y, s2 = e.x - e.y;
        const float d1 = o2.x + o2.y, d2 = o2.x - o2.y;
        const size_t base = ((size_t)(ob + k) * NT + t) * NP;
        out[base + p]       = s1 + d1;
        out[base + 256 + p] = s1 - d1;
        out[base + 256 - p] = s2 - d2;
        if (p) out[base + 512 - p] = s2 + d2;
    }

    {
        const int seg = p >> 4, o = p & 15;
        float u = 0.0f, v = 0.0f;
#pragma unroll
        for (int k = 0; k < 16; k++) {
            const int m = seg * 16 + k;
            float2 val = upk(sAB[m * 16 + o]);
            if (m & 1) v += (m & 2) ? -val.y : val.y;
            else       u += (m & 2) ? -val.x : val.x;
        }
        redu[seg][o] = u; redv[seg][o] = v;
        __syncthreads();
        if (seg == 0) {
            float U = 0.0f, V = 0.0f;
#pragma unroll
            for (int s = 0; s < 8; s++) { U += redu[s][o]; V += redv[s][o]; }
            const size_t base = ((size_t)(ob + o) * NT + t) * NP;
            out[base + 128] = U + V;
            out[base + 384] = U - V;
        }
    }
}

// ============================================================
extern "C" void kernel_launch(void* const* d_in, const int* in_sizes, int n_in,
                              void* d_out, int out_size) {
    const float* x   = (const float*)d_in[0];
    const float* Wr  = (const float*)d_in[1];
    const float* Wi  = (const float*)d_in[2];
    const float* leg = (const float*)d_in[3];
    const float* wq  = (const float*)d_in[4];
    float* out = (float*)d_out;

    cudaFuncSetAttribute(k1_dft,      cudaFuncAttributeMaxDynamicSharedMemorySize, 65536);
    cudaFuncSetAttribute(k2_analysis, cudaFuncAttributeMaxDynamicSharedMemorySize, 65536);
    cudaFuncSetAttribute(k4_synth,    cudaFuncAttributeMaxDynamicSharedMemorySize, 49152);

    cudaLaunchAttribute pdl[1];
    pdl[0].id = cudaLaunchAttributeProgrammaticStreamSerialization;
    pdl[0].val.programmaticStreamSerializationAllowed = 1;

    k1_dft<<<256, 256, 65536>>>(x, wq);

    {
        cudaLaunchConfig_t c{};
        c.gridDim = dim3(64, 4); c.blockDim = dim3(256);
        c.dynamicSmemBytes = 65536; c.stream = 0;
        c.attrs = pdl; c.numAttrs = 1;
        cudaLaunchKernelEx(&c, k2_analysis, leg);
    }
    {
        cudaLaunchConfig_t c{};
        c.gridDim = dim3(8256); c.blockDim = dim3(256);
        c.dynamicSmemBytes = 0; c.stream = 0;
        c.attrs = pdl; c.numAttrs = 1;
        cudaLaunchKernelEx(&c, k3_mix, Wr, Wi);
    }
    {
        cudaLaunchConfig_t c{};
        c.gridDim = dim3(128, 4); c.blockDim = dim3(256);
        c.dynamicSmemBytes = 49152; c.stream = 0;
        c.attrs = pdl; c.numAttrs = 1;
        cudaLaunchKernelEx(&c, k4_synth, leg);
    }
    {
        cudaLaunchConfig_t c{};
        c.gridDim = dim3(256, 2); c.blockDim = dim3(128);
        c.dynamicSmemBytes = 0; c.stream = 0;
        c.attrs = pdl; c.numAttrs = 1;
        cudaLaunchKernelEx(&c, k5_idft, out);
    }
}

// round 17
// speedup vs baseline: 1.6771x; 1.0308x over previous
#include <cuda_runtime.h>
#include <math.h>

#define NT 256   // ntheta
#define NP 512   // nphi
#define NC 32    // channels
#define NL 128   // L

typedef unsigned long long u64;

// ---------- packed f32x2 helpers (sm_103a FFMA2) ----------
__device__ __forceinline__ u64 pk2(float a, float b) {
    u64 r; asm("mov.b64 %0,{%1,%2};" : "=l"(r) : "f"(a), "f"(b)); return r;
}
__device__ __forceinline__ float2 upk(u64 v) {
    float2 f; asm("mov.b64 {%0,%1},%2;" : "=f"(f.x), "=f"(f.y) : "l"(v)); return f;
}
__device__ __forceinline__ u64 fma2(u64 a, u64 b, u64 c) {
    u64 d; asm("fma.rn.f32x2 %0,%1,%2,%3;" : "=l"(d) : "l"(a), "l"(b), "l"(c)); return d;
}
__device__ __forceinline__ u64 mul2(u64 a, u64 b) {
    u64 d; asm("mul.rn.f32x2 %0,%1,%2;" : "=l"(d) : "l"(a), "l"(b)); return d;
}
// ---------- PDL ----------
__device__ __forceinline__ void gdc_launch() {
    asm volatile("griddepcontrol.launch_dependents;" ::: "memory");
}
__device__ __forceinline__ void gdc_wait() {
    asm volatile("griddepcontrol.wait;" ::: "memory");
}

// ---------- static device scratch ----------
__device__ u64 g_F  [NT][NL][NC];
__device__ u64 g_flm[NL][NL][NC];
__device__ u64 g_uv [NL][NL][NC];
__device__ u64 g_AB [NT][NL][NC];

// ============================================================
// K1: forward DFT over phi, radix-2 + q-reflection folded.
// grid 256 (t), block 256 = 128 m-slots x 2 channel-groups (16 ch each).
// ============================================================
__global__ __launch_bounds__(256) void k1_dft(const float* __restrict__ x,
                                              const float* __restrict__ wq) {
    gdc_launch();
    extern __shared__ u64 sm1[];
    u64* ype = sm1;
    u64* ymo = sm1 + 4096;

    const int t    = blockIdx.x;
    const int tid  = threadIdx.x;
    const int lane = tid & 31;
    const int cg   = tid >> 7;              // channel group 0/1
    const int wm   = (tid & 127) >> 5;      // 0..3
    const int par  = wm >> 1;               // 0: even m, 1: odd m
    const int m    = 2 * (((wm & 1) << 5) + lane) + par;

    {
        const float s = wq[t] * (2.0f * (float)M_PI / 512.0f);
        const float4* x4 = (const float4*)(x + (size_t)t * NP * NC);
        for (int i = tid; i < 2048; i += 256) {
            float4 a = x4[i];
            float4 b = x4[i + 2048];
            const int p = i >> 3, j = i & 7;
            ype[p * 16 + j * 2]     = pk2((a.x + b.x) * s, (a.y + b.y) * s);
            ype[p * 16 + j * 2 + 1] = pk2((a.z + b.z) * s, (a.w + b.w) * s);
            ymo[p * 16 + j * 2]     = pk2((a.x - b.x) * s, (a.y - b.y) * s);
            ymo[p * 16 + j * 2 + 1] = pk2((a.z - b.z) * s, (a.w - b.w) * s);
        }
    }
    __syncthreads();

    {
        const u64 ONE2 = pk2(1.0f, 1.0f), NEG2 = pk2(-1.0f, -1.0f);
        for (int i = tid; i < 4096; i += 256) {
            const int q = (i >> 4) & 127;
            if (q == 0) continue;
            u64* base = sm1 + ((i >> 11) << 12);
            const int j  = i & 15;
            const int ia = q * 16 + j, ib = (256 - q) * 16 + j;
            u64 a = base[ia], b = base[ib];
            base[ia] = fma2(b, ONE2, a);
            base[ib] = fma2(b, NEG2, a);
        }
    }
    __syncthreads();

    const u64* yrow = (par ? ymo : ype) + cg * 8;

    float sd, cd;
    sincosf(-(float)M_PI / 256.0f * (float)m, &sd, &cd);
    u64 CDD = pk2(cd, cd), SDD = pk2(sd, sd), NSD = pk2(-sd, -sd);
    u64 CC = pk2(cd, cd), SS = pk2(sd, sd);   // state at q=1

    u64 aR[8], aI[8];
#pragma unroll
    for (int k = 0; k < 8; k++) { aR[k] = 0ull; aI[k] = 0ull; }

    const u64* pR = yrow + (par ? 255 * 16 : 16);
    const u64* pI = yrow + (par ? 16 : 255 * 16);
    const int  sR = par ? -16 : 16;

#pragma unroll 4
    for (int q = 1; q < 128; q++) {
        const ulonglong2* rR = (const ulonglong2*)pR;
        const ulonglong2* rI = (const ulonglong2*)pI;
#pragma unroll
        for (int k = 0; k < 4; k++) {
            ulonglong2 vR = rR[k];
            ulonglong2 vI = rI[k];
            aR[2 * k]     = fma2(vR.x, CC, aR[2 * k]);
            aR[2 * k + 1] = fma2(vR.y, CC, aR[2 * k + 1]);
            aI[2 * k]     = fma2(vI.x, SS, aI[2 * k]);
            aI[2 * k + 1] = fma2(vI.y, SS, aI[2 * k + 1]);
        }
        u64 t1 = mul2(SS, NSD);
        u64 nC = fma2(CC, CDD, t1);
        u64 t2 = mul2(CC, SDD);
        SS = fma2(SS, CDD, t2);
        CC = nC;
        pR += sR; pI -= sR;
    }

    {
        const ulonglong2* r0 = (const ulonglong2*)yrow;
        const ulonglong2* rh = (const ulonglong2*)(yrow + 128 * 16);
        const float sg = ((m >> 1) & 1) ? -1.0f : 1.0f;
        const u64 ONE2 = pk2(1.0f, 1.0f);
        if (!par) {
            const u64 SG = pk2(sg, sg);
#pragma unroll
            for (int k = 0; k < 4; k++) {
                ulonglong2 v0 = r0[k], vh = rh[k];
                aR[2 * k]     = fma2(v0.x, ONE2, aR[2 * k]);
                aR[2 * k + 1] = fma2(v0.y, ONE2, aR[2 * k + 1]);
                aR[2 * k]     = fma2(vh.x, SG, aR[2 * k]);
                aR[2 * k + 1] = fma2(vh.y, SG, aR[2 * k + 1]);
            }
        } else {
            const u64 SG = pk2(-sg, -sg);
#pragma unroll
            for (int k = 0; k < 4; k++) {
                ulonglong2 v0 = r0[k], vh = rh[k];
                aR[2 * k]     = fma2(v0.x, ONE2, aR[2 * k]);
                aR[2 * k + 1] = fma2(v0.y, ONE2, aR[2 * k + 1]);
                aI[2 * k]     = fma2(vh.x, SG, aI[2 * k]);
                aI[2 * k + 1] = fma2(vh.y, SG, aI[2 * k + 1]);
            }
        }
    }

    ulonglong2* fout = (ulonglong2*)&g_F[t][m][cg * 16];
#pragma unroll
    for (int k = 0; k < 8; k++) {
        float2 r = upk(aR[k]), i2 = upk(aI[k]);
        fout[k] = make_ulonglong2(pk2(r.x, i2.x), pk2(r.y, i2.y));
    }
}

// ============================================================
// K2: Legendre analysis, theta-parity folded. Half moved to grid z:
// grid (64 mp, 4 lh, 2 half), block 256 — one m per block, one stage,
// one barrier; empty l-quarters exit before staging.
// ============================================================
__global__ __launch_bounds__(256) void k2_analysis(const float* __restrict__ leg) {
    gdc_launch();
    extern __shared__ u64 sm2[];
    u64* Fp = sm2;
    u64* Fm = sm2 + 128 * 32;

    const int mp   = blockIdx.x;
    const int lh   = blockIdx.y;
    const int half = blockIdx.z;
    const int tid  = threadIdx.x;
    const int w    = tid >> 5;
    const int lane = tid & 31;

    const int m  = half ? (127 - mp) : mp;
    const int nl = NL - m;
    if (lh * 32 >= nl) return;      // whole quarter empty

    gdc_wait();

    for (int i = tid; i < 128 * 32; i += 256) {
        const int t = i >> 5, c = i & 31;
        float2 a = upk(g_F[t][m][c]);
        float2 b = upk(g_F[255 - t][m][c]);
        Fp[i] = pk2(a.x + b.x, a.y + b.y);
        Fm[i] = pk2(a.x - b.x, a.y - b.y);
    }
    __syncthreads();

    const int li = (lh * 8 + w) * 4;
    if (li < nl) {
        u64 acc[4] = {0ull, 0ull, 0ull, 0ull};
        const int lmax = min(4, nl - li);
        const float* bp[4];
#pragma unroll
        for (int k = 0; k < 4; k++) {
            int l = m + li + k; if (l > 127) l = 127;
            bp[k] = leg + ((size_t)l * 255 + (127 + m)) * NT;
        }
#pragma unroll 4
        for (int t = 0; t < 128; t++) {
            u64 fp = Fp[t * 32 + lane];
            u64 fm = Fm[t * 32 + lane];
#pragma unroll
            for (int k = 0; k < 4; k++) {
                float b = __ldg(bp[k] + t);
                acc[k] = fma2(pk2(b, b), (k & 1) ? fm : fp, acc[k]);
            }
        }
        for (int k = 0; k < lmax; k++)
            g_flm[m][m + li + k][lane] = acc[k];
    }
}

// ============================================================
// K3: channel mix; 1D grid over the 8256 valid (l,m) pairs only.
// Weight prefetch before gdc_wait overlaps K2.
// ============================================================
__global__ __launch_bounds__(256) void k3_mix(const float* __restrict__ Wr,
                                              const float* __restrict__ Wi) {
    gdc_launch();
    const int i = blockIdx.x;
    int l = (int)((sqrtf(8.0f * (float)i + 1.0f) - 1.0f) * 0.5f);
    while ((l + 1) * (l + 2) / 2 <= i) ++l;
    while (l * (l + 1) / 2 > i) --l;
    const int m = i - l * (l + 1) / 2;

    __shared__ float2 sf[32];
    __shared__ float2 red[8][32];
    const int tid = threadIdx.x, w = tid >> 5, lane = tid & 31;

    const size_t bp = ((size_t)l * 255 + (127 + m)) * 1024;
    const size_t bn = ((size_t)l * 255 + (127 - m)) * 1024;

    float S[4], D[4];
#pragma unroll
    for (int k = 0; k < 4; k++) {
        const int c = w * 4 + k;
        const size_t op = bp + (size_t)c * 32 + lane;
        float wr = __ldcs(Wr + op);
        float wi = __ldcs(Wi + op);
        if (m) {
            const size_t on = bn + (size_t)c * 32 + lane;
            S[k] = wr + __ldcs(Wr + on);
            D[k] = __ldcs(Wi + on) - wi;
        } else {
            S[k] = wr; D[k] = -wi;
        }
    }

    gdc_wait();

    if (tid < 32) sf[tid] = ((const float2*)&g_flm[m][l][0])[tid];
    __syncthreads();

    float U = 0.0f, V = 0.0f;
#pragma unroll
    for (int k = 0; k < 4; k++) {
        const int c = w * 4 + k;
        const float fr = sf[c].x, fi = sf[c].y;
        U += fr * S[k]; U += fi * D[k];
        V += fr * D[k]; V -= fi * S[k];
    }
    red[w][lane] = make_float2(U, V);
    __syncthreads();
    if (w == 0) {
        float2 a = red[0][lane];
#pragma unroll
        for (int k = 1; k < 8; k++) { a.x += red[k][lane].x; a.y += red[k][lane].y; }
        g_uv[m][l][lane] = pk2(a.x, a.y);
    }
}

// ============================================================
// K4: Legendre synthesis, all-smem inner loop (R16 proven config).
// grid (128 m, 4 tg), block 256. dynamic smem 48KB.
// ============================================================
__global__ __launch_bounds__(256) void k4_synth(const float* __restrict__ leg) {
    gdc_launch();
    extern __shared__ u64 sm4[];
    u64*   suv = sm4;                       // [128][32] u64   (32KB)
    float* sP  = (float*)(sm4 + 128 * 32);  // [128][32] float (16KB)

    const int m   = blockIdx.x;
    const int tg  = blockIdx.y;
    const int nl  = NL - m;
    const int nlp = (nl + 3) & ~3;
    const int tid = threadIdx.x, w = tid >> 5, lane = tid & 31;
    const int tb  = w * 4;

    const float* Pp = leg + ((size_t)m * 255 + (127 + m)) * NT + tg * 32;
    for (int i = tid; i < nlp * 32; i += 256) {
        const int il = i >> 5, tt = i & 31;
        sP[i] = (il < nl) ? __ldg(Pp + (size_t)il * (255 * NT) + tt) : 0.0f;
    }

    gdc_wait();   // g_uv ready

    const u64* uvp = &g_uv[m][m][0];
    for (int i = tid; i < nlp * 32; i += 256)
        suv[i] = (i < nl * 32) ? uvp[i] : 0ull;
    __syncthreads();

    u64 E[4] = {0ull, 0ull, 0ull, 0ull};
    u64 O[4] = {0ull, 0ull, 0ull, 0ull};

#pragma unroll 4
    for (int il = 0; il < nlp; il += 2) {
        const u64 uv0 = suv[il * 32 + lane];
        const u64 uv1 = suv[(il + 1) * 32 + lane];
        const float4 P0 = *(const float4*)(sP + il * 32 + tb);
        const float4 P1 = *(const float4*)(sP + (il + 1) * 32 + tb);
        E[0] = fma2(pk2(P0.x, P0.x), uv0, E[0]);
        E[1] = fma2(pk2(P0.y, P0.y), uv0, E[1]);
        E[2] = fma2(pk2(P0.z, P0.z), uv0, E[2]);
        E[3] = fma2(pk2(P0.w, P0.w), uv0, E[3]);
        O[0] = fma2(pk2(P1.x, P1.x), uv1, O[0]);
        O[1] = fma2(pk2(P1.y, P1.y), uv1, O[1]);
        O[2] = fma2(pk2(P1.z, P1.z), uv1, O[2]);
        O[3] = fma2(pk2(P1.w, P1.w), uv1, O[3]);
    }

#pragma unroll
    for (int j = 0; j < 4; j++) {
        const int t = tg * 32 + tb + j;
        float2 e = upk(E[j]), o2 = upk(O[j]);
        g_AB[t][m][lane]       = pk2(e.x + o2.x, e.y + o2.y);
        g_AB[255 - t][m][lane] = pk2(e.x - o2.x, e.y - o2.y);
    }
}

// ============================================================
// K5: inverse transform, m-parity + p-reflection folded, edge fused.
// o-groups split 4-way: grid (256 t, 4 og), block 128 (p), 8KB stage.
// ============================================================
__global__ __launch_bounds__(128) void k5_idft(float* __restrict__ out) {
    __shared__ u64 sAB[128 * 8];     // 8 KB
    __shared__ float redu[16][8], redv[16][8];
    const int t  = blockIdx.x;
    const int ob = blockIdx.y * 8;
    const int p  = threadIdx.x;      // 0..127

    gdc_wait();

    for (int i = p; i < 128 * 8; i += 128) {
        const int m = i >> 3, o = i & 7;
        sAB[i] = g_AB[t][m][ob + o];
    }
    __syncthreads();

    u64 E[8], O[8];
#pragma unroll
    for (int k = 0; k < 8; k++) { E[k] = 0ull; O[k] = 0ull; }

    float sd, cd;
    sincosf(((float)M_PI / 256.0f) * (float)p, &sd, &cd);
    u64 CDD = pk2(cd, cd);
    u64 P1 = pk2(-sd, sd), P2 = pk2(sd, -sd);
    u64 cs = pk2(1.0f, 0.0f), sc = pk2(0.0f, 1.0f);

#pragma unroll 4
    for (int m = 0; m < 128; m += 2) {
        const ulonglong2* r0 = (const ulonglong2*)(sAB + m * 8);
#pragma unroll
        for (int k = 0; k < 4; k++) {
            ulonglong2 v = r0[k];
            E[2 * k]     = fma2(v.x, cs, E[2 * k]);
            E[2 * k + 1] = fma2(v.y, cs, E[2 * k + 1]);
        }
        { u64 t1 = mul2(sc, P1); u64 nc = fma2(cs, CDD, t1);
          u64 t2 = mul2(cs, P2); sc = fma2(sc, CDD, t2); cs = nc; }

        const ulonglong2* r1 = (const ulonglong2*)(sAB + (m + 1) * 8);
#pragma unroll
        for (int k = 0; k < 4; k++) {
            ulonglong2 v = r1[k];
            O[2 * k]     = fma2(v.x, cs, O[2 * k]);
            O[2 * k + 1] = fma2(v.y, cs, O[2 * k + 1]);
        }
        { u64 t1 = mul2(sc, P1); u64 nc = fma2(cs, CDD, t1);
          u64 t2 = mul2(cs, P2); sc = fma2(sc, CDD, t2); cs = nc; }
    }

#pragma unroll
    for (int k = 0; k < 8; k++) {
        float2 e = upk(E[k]), o2 = upk(O[k]);
        const float s1 = e.x + e.y, s2 = e.x - e.y;
        const float d1 = o2.x + o2.y, d2 = o2.x - o2.y;
        const size_t base = ((size_t)(ob + k) * NT + t) * NP;
        out[base + p]       = s1 + d1;
        out[base + 256 + p] = s1 - d1;
        out[base + 256 - p] = s2 - d2;
        if (p) out[base + 512 - p] = s2 + d2;
    }

    // ---- fused edge columns p=128, 384 (16 segs x 8 channels) ----
    {
        const int seg = p >> 3, o = p & 7;
        float u = 0.0f, v = 0.0f;
#pragma unroll
        for (int k = 0; k < 8; k++) {
            const int m = seg * 8 + k;
            float2 val = upk(sAB[m * 8 + o]);
            if (m & 1) v += (m & 2) ? -val.y : val.y;
            else       u += (m & 2) ? -val.x : val.x;
        }
        redu[seg][o] = u; redv[seg][o] = v;
        __syncthreads();
        if (seg == 0) {
            float U = 0.0f, V = 0.0f;
#pragma unroll
            for (int s = 0; s < 16; s++) { U += redu[s][o]; V += redv[s][o]; }
            const size_t base = ((size_t)(ob + o) * NT + t) * NP;
            out[base + 128] = U + V;
            out[base + 384] = U - V;
        }
    }
}

// ============================================================
extern "C" void kernel_launch(void* const* d_in, const int* in_sizes, int n_in,
                              void* d_out, int out_size) {
    const float* x   = (const float*)d_in[0];
    const float* Wr  = (const float*)d_in[1];
    const float* Wi  = (const float*)d_in[2];
    const float* leg = (const float*)d_in[3];
    const float* wq  = (const float*)d_in[4];
    float* out = (float*)d_out;

    cudaFuncSetAttribute(k1_dft,      cudaFuncAttributeMaxDynamicSharedMemorySize, 65536);
    cudaFuncSetAttribute(k2_analysis, cudaFuncAttributeMaxDynamicSharedMemorySize, 65536);
    cudaFuncSetAttribute(k4_synth,    cudaFuncAttributeMaxDynamicSharedMemorySize, 49152);

    cudaLaunchAttribute pdl[1];
    pdl[0].id = cudaLaunchAttributeProgrammaticStreamSerialization;
    pdl[0].val.programmaticStreamSerializationAllowed = 1;

    k1_dft<<<256, 256, 65536>>>(x, wq);

    {
        cudaLaunchConfig_t c{};
        c.gridDim = dim3(64, 4, 2); c.blockDim = dim3(256);
        c.dynamicSmemBytes = 65536; c.stream = 0;
        c.attrs = pdl; c.numAttrs = 1;
        cudaLaunchKernelEx(&c, k2_analysis, leg);
    }
    {
        cudaLaunchConfig_t c{};
        c.gridDim = dim3(8256); c.blockDim = dim3(256);
        c.dynamicSmemBytes = 0; c.stream = 0;
        c.attrs = pdl; c.numAttrs = 1;
        cudaLaunchKernelEx(&c, k3_mix, Wr, Wi);
    }
    {
        cudaLaunchConfig_t c{};
        c.gridDim = dim3(128, 4); c.blockDim = dim3(256);
        c.dynamicSmemBytes = 49152; c.stream = 0;
        c.attrs = pdl; c.numAttrs = 1;
        cudaLaunchKernelEx(&c, k4_synth, leg);
    }
    {
        cudaLaunchConfig_t c{};
        c.gridDim = dim3(256, 4); c.blockDim = dim3(128);
        c.dynamicSmemBytes = 0; c.stream = 0;
        c.attrs = pdl; c.numAttrs = 1;
        cudaLaunchKernelEx(&c, k5_idft, out);
    }
}